// round 1
// baseline (speedup 1.0000x reference)
#include <cuda_runtime.h>
#include <cstdint>

// ---------------- problem constants ----------------
#define BS   6
#define NQ   4096
#define EMB  256
#define NH   8
#define DH   32
#define NL   4
#define NP   8
#define LTOT 19560            // 92*160 + 46*80 + 23*40 + 12*20
#define MQ   (BS * NQ)        // 24576
#define MV   (BS * LTOT)      // 117360

// ---------------- scratch (device globals; no cudaMalloc allowed) ----------
__device__ float g_v   [(size_t)MV * EMB];   // projected value  [b*LTOT+l][256]
__device__ float g_off [(size_t)MQ * 512];   // raw offsets      [b*Q+q][512]
__device__ float g_attn[(size_t)MQ * 256];   // raw attn logits  [b*Q+q][256]
__device__ float g_tmp [(size_t)MQ * EMB];   // sampled output   [b*Q+q][256]

// ---------------- generic tiled fp32 GEMM:  C = A(MxK) * B(KxN) + bias -----
// BM=128, BN=64, BK=16, 256 threads, 8x4 accum per thread.
__global__ __launch_bounds__(256)
void gemm_bias_kernel(const float* __restrict__ A, const float* __restrict__ B,
                      const float* __restrict__ bias, float* __restrict__ C,
                      int M, int N, int K)
{
    __shared__ float As[16][128];
    __shared__ float Bs[16][64];

    const int tid  = threadIdx.x;
    const int tx   = tid & 15;        // 0..15 -> 4 cols each
    const int ty   = tid >> 4;        // 0..15 -> 8 rows each
    const int row0 = blockIdx.y * 128;
    const int col0 = blockIdx.x * 64;

    float acc[8][4];
#pragma unroll
    for (int m = 0; m < 8; ++m)
#pragma unroll
        for (int n = 0; n < 4; ++n) acc[m][n] = 0.f;

    for (int k0 = 0; k0 < K; k0 += 16) {
        // A tile: 128 rows x 16 cols, float4 loads (2 per thread)
#pragma unroll
        for (int it = 0; it < 2; ++it) {
            int idx = tid + it * 256;          // 0..511
            int r   = idx >> 2;                // 0..127
            int c4  = (idx & 3) << 2;          // 0,4,8,12
            int gr  = row0 + r;
            float4 av = make_float4(0.f, 0.f, 0.f, 0.f);
            if (gr < M)
                av = *(const float4*)(A + (size_t)gr * K + k0 + c4);
            As[c4 + 0][r] = av.x;
            As[c4 + 1][r] = av.y;
            As[c4 + 2][r] = av.z;
            As[c4 + 3][r] = av.w;
        }
        // B tile: 16 rows x 64 cols, one float4 per thread
        {
            int r  = tid >> 4;                 // 0..15
            int c4 = (tid & 15) << 2;          // 0..60
            *(float4*)(&Bs[r][c4]) =
                *(const float4*)(B + (size_t)(k0 + r) * N + col0 + c4);
        }
        __syncthreads();

#pragma unroll
        for (int k = 0; k < 16; ++k) {
            float a[8], b[4];
#pragma unroll
            for (int m = 0; m < 8; ++m) a[m] = As[k][ty * 8 + m];
#pragma unroll
            for (int n = 0; n < 4; ++n) b[n] = Bs[k][tx * 4 + n];
#pragma unroll
            for (int m = 0; m < 8; ++m)
#pragma unroll
                for (int n = 0; n < 4; ++n)
                    acc[m][n] = fmaf(a[m], b[n], acc[m][n]);
        }
        __syncthreads();
    }

    float4 bv = *(const float4*)(bias + col0 + tx * 4);
#pragma unroll
    for (int m = 0; m < 8; ++m) {
        int gr = row0 + ty * 8 + m;
        if (gr < M) {
            float4 o;
            o.x = acc[m][0] + bv.x;
            o.y = acc[m][1] + bv.y;
            o.z = acc[m][2] + bv.z;
            o.w = acc[m][3] + bv.w;
            *(float4*)(C + (size_t)gr * N + col0 + tx * 4) = o;
        }
    }
}

// ---------------- deformable sampling core --------------------------------
// grid = BS*NQ blocks, block = (32, 8): warp = one head, lane = channel d.
__global__ __launch_bounds__(256)
void msda_sample_kernel(const float* __restrict__ refp)
{
    const int bq   = blockIdx.x;          // b*NQ + q
    const int lane = threadIdx.x;         // 0..31 = channel
    const int h    = threadIdx.y;         // 0..7  = head
    const int b    = bq >> 12;            // NQ = 4096

    // ---- softmax over the 32 attention logits of this (b,q,h) ----
    const float aval = g_attn[(size_t)bq * 256 + h * 32 + lane];
    float mx = aval;
#pragma unroll
    for (int s = 16; s; s >>= 1) mx = fmaxf(mx, __shfl_xor_sync(0xffffffffu, mx, s));
    const float e = __expf(aval - mx);
    float sm = e;
#pragma unroll
    for (int s = 16; s; s >>= 1) sm += __shfl_xor_sync(0xffffffffu, sm, s);
    const float aw = e / sm;              // lane j holds weight of point j

    // ---- offsets: lane j holds (ox, oy) of point j ----
    const float2 o2 = *(const float2*)(g_off + (size_t)bq * 512 + h * 64 + lane * 2);

    // ---- reference points: lanes 0..7 hold refp[b,q,lv,{x,y}] ----
    const float rp = (lane < 8) ? refp[(size_t)bq * 8 + lane] : 0.f;

    constexpr int   HL [4] = {92, 46, 23, 12};
    constexpr int   WL [4] = {160, 80, 40, 20};
    constexpr int   ST [4] = {0, 14720, 18400, 19320};
    constexpr float IW [4] = {1.f/160.f, 1.f/80.f, 1.f/40.f, 1.f/20.f};
    constexpr float IH [4] = {1.f/92.f,  1.f/46.f, 1.f/23.f, 1.f/12.f};

    float acc = 0.f;
    const float* vb = g_v + (size_t)b * LTOT * EMB + h * 32 + lane;

#pragma unroll
    for (int lv = 0; lv < 4; ++lv) {
        const float rx = __shfl_sync(0xffffffffu, rp, lv * 2);
        const float ry = __shfl_sync(0xffffffffu, rp, lv * 2 + 1);
        const int   Wl = WL[lv], Hl = HL[lv];
        const float* vl = vb + (size_t)ST[lv] * EMB;
#pragma unroll
        for (int p = 0; p < 8; ++p) {
            const int j = lv * 8 + p;
            const float ox = __shfl_sync(0xffffffffu, o2.x, j);
            const float oy = __shfl_sync(0xffffffffu, o2.y, j);
            const float w  = __shfl_sync(0xffffffffu, aw,  j);

            // mirror reference arithmetic: loc = ref + off/W; x = (2*loc)*(W/2) - 0.5
            const float locx = rx + ox * IW[lv];
            const float locy = ry + oy * IH[lv];
            const float gx = 2.f * locx - 1.f;
            const float gy = 2.f * locy - 1.f;
            const float x = (gx + 1.f) * ((float)Wl * 0.5f) - 0.5f;
            const float y = (gy + 1.f) * ((float)Hl * 0.5f) - 0.5f;

            const float xf = floorf(x), yf = floorf(y);
            const float wx = x - xf,    wy = y - yf;
            const int x0 = (int)xf, y0 = (int)yf;

            const bool xi0 = (x0 >= 0)  && (x0 < Wl);
            const bool xi1 = (x0 >= -1) && (x0 < Wl - 1);
            const bool yi0 = (y0 >= 0)  && (y0 < Hl);
            const bool yi1 = (y0 >= -1) && (y0 < Hl - 1);

            float v00 = 0.f, v10 = 0.f, v01 = 0.f, v11 = 0.f;
            if (yi0) {
                const float* r0 = vl + (size_t)(y0 * Wl) * EMB;
                if (xi0) v00 = r0[(size_t)x0 * EMB];
                if (xi1) v10 = r0[(size_t)(x0 + 1) * EMB];
            }
            if (yi1) {
                const float* r1 = vl + (size_t)((y0 + 1) * Wl) * EMB;
                if (xi0) v01 = r1[(size_t)x0 * EMB];
                if (xi1) v11 = r1[(size_t)(x0 + 1) * EMB];
            }

            const float s = v00 * (1.f - wx) * (1.f - wy)
                          + v10 * wx         * (1.f - wy)
                          + v01 * (1.f - wx) * wy
                          + v11 * wx         * wy;
            acc = fmaf(w, s, acc);
        }
    }
    g_tmp[(size_t)bq * EMB + h * 32 + lane] = acc;
}

// ---------------- launch ---------------------------------------------------
extern "C" void kernel_launch(void* const* d_in, const int* in_sizes, int n_in,
                              void* d_out, int out_size)
{
    const float* query  = (const float*)d_in[0];
    const float* value  = (const float*)d_in[1];
    const float* refp   = (const float*)d_in[2];
    // d_in[3] = spatial_shapes (int32) — compile-time constants, unused
    const float* W_off  = (const float*)d_in[4];
    const float* b_off  = (const float*)d_in[5];
    const float* W_attn = (const float*)d_in[6];
    const float* b_attn = (const float*)d_in[7];
    const float* W_val  = (const float*)d_in[8];
    const float* b_val  = (const float*)d_in[9];
    const float* W_out  = (const float*)d_in[10];
    const float* b_out  = (const float*)d_in[11];
    float* out = (float*)d_out;

    float *gv, *goff, *gattn, *gtmp;
    cudaGetSymbolAddress((void**)&gv,    g_v);
    cudaGetSymbolAddress((void**)&goff,  g_off);
    cudaGetSymbolAddress((void**)&gattn, g_attn);
    cudaGetSymbolAddress((void**)&gtmp,  g_tmp);

    dim3 blk(256);

    // 1) value projection: [117360,256] @ [256,256] + b_val -> g_v
    gemm_bias_kernel<<<dim3(EMB / 64, (MV + 127) / 128), blk>>>(
        value, W_val, b_val, gv, MV, EMB, EMB);

    // 2) offsets: [24576,256] @ [256,512] + b_off -> g_off
    gemm_bias_kernel<<<dim3(512 / 64, MQ / 128), blk>>>(
        query, W_off, b_off, goff, MQ, 512, EMB);

    // 3) attention logits: [24576,256] @ [256,256] + b_attn -> g_attn
    gemm_bias_kernel<<<dim3(EMB / 64, MQ / 128), blk>>>(
        query, W_attn, b_attn, gattn, MQ, EMB, EMB);

    // 4) softmax + bilinear sampling -> g_tmp
    msda_sample_kernel<<<MQ, dim3(32, 8)>>>(refp);

    // 5) output projection: [24576,256] @ [256,256] + b_out -> d_out
    gemm_bias_kernel<<<dim3(EMB / 64, MQ / 128), blk>>>(
        gtmp, W_out, b_out, out, MQ, EMB, EMB);
}

// round 2
// speedup vs baseline: 1.2546x; 1.2546x over previous
#include <cuda_runtime.h>
#include <cstdint>

// ---------------- problem constants ----------------
#define BS   6
#define NQ   4096
#define EMB  256
#define NH   8
#define DH   32
#define NL   4
#define NP   8
#define LTOT 19560            // 92*160 + 46*80 + 23*40 + 12*20
#define MQ   (BS * NQ)        // 24576
#define MV   (BS * LTOT)      // 117360

// ---------------- scratch (device globals; no cudaMalloc allowed) ----------
__device__ float g_v   [(size_t)MV * EMB];   // projected value  [b*LTOT+l][256]
__device__ float g_off [(size_t)MQ * 512];   // raw offsets      [b*Q+q][512]
__device__ float g_attn[(size_t)MQ * 256];   // raw attn logits  [b*Q+q][256]
__device__ float g_tmp [(size_t)MQ * EMB];   // sampled output   [b*Q+q][256]

__constant__ int   cHL[4] = {92, 46, 23, 12};
__constant__ int   cWL[4] = {160, 80, 40, 20};
__constant__ int   cST[4] = {0, 14720, 18400, 19320};
__constant__ float cIW[4] = {1.f/160.f, 1.f/80.f, 1.f/40.f, 1.f/20.f};
__constant__ float cIH[4] = {1.f/92.f,  1.f/46.f, 1.f/23.f, 1.f/12.f};

// ---------------- generic tiled fp32 GEMM:  C = A(MxK) * B(KxN) + bias -----
__global__ __launch_bounds__(256)
void gemm_bias_kernel(const float* __restrict__ A, const float* __restrict__ B,
                      const float* __restrict__ bias, float* __restrict__ C,
                      int M, int N, int K)
{
    __shared__ float As[16][128];
    __shared__ float Bs[16][64];

    const int tid  = threadIdx.x;
    const int tx   = tid & 15;
    const int ty   = tid >> 4;
    const int row0 = blockIdx.y * 128;
    const int col0 = blockIdx.x * 64;

    float acc[8][4];
#pragma unroll
    for (int m = 0; m < 8; ++m)
#pragma unroll
        for (int n = 0; n < 4; ++n) acc[m][n] = 0.f;

    for (int k0 = 0; k0 < K; k0 += 16) {
#pragma unroll
        for (int it = 0; it < 2; ++it) {
            int idx = tid + it * 256;
            int r   = idx >> 2;
            int c4  = (idx & 3) << 2;
            int gr  = row0 + r;
            float4 av = make_float4(0.f, 0.f, 0.f, 0.f);
            if (gr < M)
                av = *(const float4*)(A + (size_t)gr * K + k0 + c4);
            As[c4 + 0][r] = av.x;
            As[c4 + 1][r] = av.y;
            As[c4 + 2][r] = av.z;
            As[c4 + 3][r] = av.w;
        }
        {
            int r  = tid >> 4;
            int c4 = (tid & 15) << 2;
            *(float4*)(&Bs[r][c4]) =
                *(const float4*)(B + (size_t)(k0 + r) * N + col0 + c4);
        }
        __syncthreads();

#pragma unroll
        for (int k = 0; k < 16; ++k) {
            float a[8], b[4];
#pragma unroll
            for (int m = 0; m < 8; ++m) a[m] = As[k][ty * 8 + m];
#pragma unroll
            for (int n = 0; n < 4; ++n) b[n] = Bs[k][tx * 4 + n];
#pragma unroll
            for (int m = 0; m < 8; ++m)
#pragma unroll
                for (int n = 0; n < 4; ++n)
                    acc[m][n] = fmaf(a[m], b[n], acc[m][n]);
        }
        __syncthreads();
    }

    float4 bv = *(const float4*)(bias + col0 + tx * 4);
#pragma unroll
    for (int m = 0; m < 8; ++m) {
        int gr = row0 + ty * 8 + m;
        if (gr < M) {
            float4 o;
            o.x = acc[m][0] + bv.x;
            o.y = acc[m][1] + bv.y;
            o.z = acc[m][2] + bv.z;
            o.w = acc[m][3] + bv.w;
            *(float4*)(C + (size_t)gr * N + col0 + tx * 4) = o;
        }
    }
}

// ---------------- deformable sampling core --------------------------------
// grid = BS*NQ blocks, block = (32, 8): warp = one head, lane = channel d.
// Phase 1: lane == point j; compute 4 pre-scaled byte offsets (level start &
//          per-axis clamp folded in) + 4 pre-multiplied corner weights
//          (softmax weight * bilinear weight * validity), stage in smem.
// Phase 2: lane == channel; per point: 2x LDS.128 (uniform) + 4 LDG + 4 FFMA.
__global__ __launch_bounds__(256)
void msda_sample_kernel(const float* __restrict__ refp)
{
    __shared__ float4 st[NH][32][2];     // [head][point][{offs4, wts4}]

    const int bq   = blockIdx.x;          // b*NQ + q
    const int lane = threadIdx.x;         // 0..31
    const int h    = threadIdx.y;         // 0..7
    const int b    = bq >> 12;            // NQ = 4096

    // ---- softmax over the 32 attention logits of this (b,q,h) ----
    const float aval = g_attn[(size_t)bq * 256 + h * 32 + lane];
    float mx = aval;
#pragma unroll
    for (int s = 16; s; s >>= 1) mx = fmaxf(mx, __shfl_xor_sync(0xffffffffu, mx, s));
    const float e = __expf(aval - mx);
    float sm = e;
#pragma unroll
    for (int s = 16; s; s >>= 1) sm += __shfl_xor_sync(0xffffffffu, sm, s);
    const float aw = e / sm;              // lane j holds weight of point j

    // ---- per-lane (lane = point j) coordinate precompute ----
    {
        const int j  = lane;
        const int lv = j >> 3;
        const int Wl = cWL[lv], Hl = cHL[lv];

        const float2 o2 = *(const float2*)(g_off + (size_t)bq * 512 + h * 64 + j * 2);
        const float rx = refp[(size_t)bq * 8 + lv * 2];
        const float ry = refp[(size_t)bq * 8 + lv * 2 + 1];

        // mirror reference arithmetic: loc = ref + off/W; x = (2*loc)*(W/2) - 0.5
        const float locx = rx + o2.x * cIW[lv];
        const float locy = ry + o2.y * cIH[lv];
        const float gx = 2.f * locx - 1.f;
        const float gy = 2.f * locy - 1.f;
        const float x = (gx + 1.f) * ((float)Wl * 0.5f) - 0.5f;
        const float y = (gy + 1.f) * ((float)Hl * 0.5f) - 0.5f;

        const float xf = floorf(x), yf = floorf(y);
        const float wx = x - xf,    wy = y - yf;
        const int x0 = (int)xf, y0 = (int)yf;
        const int x1 = x0 + 1,  y1 = y0 + 1;

        const bool vx0 = (x0 >= 0) && (x0 < Wl);
        const bool vx1 = (x1 >= 0) && (x1 < Wl);
        const bool vy0 = (y0 >= 0) && (y0 < Hl);
        const bool vy1 = (y1 >= 0) && (y1 < Hl);

        const int xA = min(max(x0, 0), Wl - 1);
        const int xB = min(max(x1, 0), Wl - 1);
        const int yA = min(max(y0, 0), Hl - 1);
        const int yB = min(max(y1, 0), Hl - 1);

        // byte offsets into g_v row space (1024 B per spatial location)
        const int base = cST[lv];
        const int off00 = (base + yA * Wl + xA) << 10;
        const int off10 = (base + yA * Wl + xB) << 10;
        const int off01 = (base + yB * Wl + xA) << 10;
        const int off11 = (base + yB * Wl + xB) << 10;

        const float w00 = (vx0 && vy0) ? aw * (1.f - wx) * (1.f - wy) : 0.f;
        const float w10 = (vx1 && vy0) ? aw * wx         * (1.f - wy) : 0.f;
        const float w01 = (vx0 && vy1) ? aw * (1.f - wx) * wy         : 0.f;
        const float w11 = (vx1 && vy1) ? aw * wx         * wy         : 0.f;

        st[h][j][0] = make_float4(__int_as_float(off00), __int_as_float(off10),
                                  __int_as_float(off01), __int_as_float(off11));
        st[h][j][1] = make_float4(w00, w10, w01, w11);
    }
    __syncwarp();

    // ---- phase 2: lane = channel; accumulate 32 points ----
    const char* vb = (const char*)(g_v + (size_t)b * LTOT * EMB + h * 32 + lane);

    float acc = 0.f;
#pragma unroll 8
    for (int p = 0; p < 32; ++p) {
        const float4 o = st[h][p][0];
        const float4 w = st[h][p][1];
        const float v00 = *(const float*)(vb + __float_as_int(o.x));
        const float v10 = *(const float*)(vb + __float_as_int(o.y));
        const float v01 = *(const float*)(vb + __float_as_int(o.z));
        const float v11 = *(const float*)(vb + __float_as_int(o.w));
        acc = fmaf(w.x, v00, acc);
        acc = fmaf(w.y, v10, acc);
        acc = fmaf(w.z, v01, acc);
        acc = fmaf(w.w, v11, acc);
    }
    g_tmp[(size_t)bq * EMB + h * 32 + lane] = acc;
}

// ---------------- launch ---------------------------------------------------
extern "C" void kernel_launch(void* const* d_in, const int* in_sizes, int n_in,
                              void* d_out, int out_size)
{
    const float* query  = (const float*)d_in[0];
    const float* value  = (const float*)d_in[1];
    const float* refp   = (const float*)d_in[2];
    // d_in[3] = spatial_shapes (int32) — compile-time constants, unused
    const float* W_off  = (const float*)d_in[4];
    const float* b_off  = (const float*)d_in[5];
    const float* W_attn = (const float*)d_in[6];
    const float* b_attn = (const float*)d_in[7];
    const float* W_val  = (const float*)d_in[8];
    const float* b_val  = (const float*)d_in[9];
    const float* W_out  = (const float*)d_in[10];
    const float* b_out  = (const float*)d_in[11];
    float* out = (float*)d_out;

    float *gv, *goff, *gattn, *gtmp;
    cudaGetSymbolAddress((void**)&gv,    g_v);
    cudaGetSymbolAddress((void**)&goff,  g_off);
    cudaGetSymbolAddress((void**)&gattn, g_attn);
    cudaGetSymbolAddress((void**)&gtmp,  g_tmp);

    dim3 blk(256);

    // 1) value projection: [117360,256] @ [256,256] + b_val -> g_v
    gemm_bias_kernel<<<dim3(EMB / 64, (MV + 127) / 128), blk>>>(
        value, W_val, b_val, gv, MV, EMB, EMB);

    // 2) offsets: [24576,256] @ [256,512] + b_off -> g_off
    gemm_bias_kernel<<<dim3(512 / 64, MQ / 128), blk>>>(
        query, W_off, b_off, goff, MQ, 512, EMB);

    // 3) attention logits: [24576,256] @ [256,256] + b_attn -> g_attn
    gemm_bias_kernel<<<dim3(EMB / 64, MQ / 128), blk>>>(
        query, W_attn, b_attn, gattn, MQ, EMB, EMB);

    // 4) softmax + bilinear sampling -> g_tmp
    msda_sample_kernel<<<MQ, dim3(32, 8)>>>(refp);

    // 5) output projection: [24576,256] @ [256,256] + b_out -> d_out
    gemm_bias_kernel<<<dim3(EMB / 64, MQ / 128), blk>>>(
        gtmp, W_out, b_out, out, MQ, EMB, EMB);
}

// round 3
// speedup vs baseline: 1.4232x; 1.1344x over previous
#include <cuda_runtime.h>
#include <cstdint>

// ---------------- problem constants ----------------
#define BS   6
#define NQ   4096
#define EMB  256
#define NH   8
#define DH   32
#define NL   4
#define NP   8
#define LTOT 19560            // 92*160 + 46*80 + 23*40 + 12*20
#define MQ   (BS * NQ)        // 24576
#define MV   (BS * LTOT)      // 117360

// ---------------- scratch (device globals; no cudaMalloc allowed) ----------
__device__ float g_v   [(size_t)MV * EMB];   // projected value  [b*LTOT+l][256]
__device__ float g_off [(size_t)MQ * 512];   // raw offsets      [b*Q+q][512]
__device__ float g_attn[(size_t)MQ * 256];   // raw attn logits  [b*Q+q][256]
__device__ float g_tmp [(size_t)MQ * EMB];   // sampled output   [b*Q+q][256]

__constant__ int   cHL[4] = {92, 46, 23, 12};
__constant__ int   cWL[4] = {160, 80, 40, 20};
__constant__ int   cST[4] = {0, 14720, 18400, 19320};
__constant__ float cIW[4] = {1.f/160.f, 1.f/80.f, 1.f/40.f, 1.f/20.f};
__constant__ float cIH[4] = {1.f/92.f,  1.f/46.f, 1.f/23.f, 1.f/12.f};

// ---------------- tiled fp32 GEMM:  C = A(MxK) * B(KxN) + bias -------------
// BM=128, BN=128, BK=16, 256 threads, 8x8 accum per thread (2x2 blocks of
// 4x4 so every shared read is a conflict-free LDS.128).
__global__ __launch_bounds__(256, 2)
void gemm_bias_kernel(const float* __restrict__ A, const float* __restrict__ B,
                      const float* __restrict__ bias, float* __restrict__ C,
                      int M, int N, int K)
{
    __shared__ float As[16][132];   // padded: transpose-store conflicts -> 2-way
    __shared__ float Bs[16][128];

    const int tid  = threadIdx.x;
    const int tx   = tid & 15;        // 16 cols of threads
    const int ty   = tid >> 4;        // 16 rows of threads
    const int row0 = blockIdx.y * 128;
    const int col0 = blockIdx.x * 128;

    float acc[2][2][4][4];
#pragma unroll
    for (int g = 0; g < 2; ++g)
#pragma unroll
        for (int h = 0; h < 2; ++h)
#pragma unroll
            for (int i = 0; i < 4; ++i)
#pragma unroll
                for (int j = 0; j < 4; ++j) acc[g][h][i][j] = 0.f;

    for (int k0 = 0; k0 < K; k0 += 16) {
        // A tile: 128 rows x 16 k, transposed into As[k][row]
#pragma unroll
        for (int it = 0; it < 2; ++it) {
            int idx = tid + it * 256;          // 0..511
            int r   = idx >> 2;                // 0..127
            int c4  = (idx & 3) << 2;          // 0,4,8,12
            int gr  = row0 + r;
            float4 av = make_float4(0.f, 0.f, 0.f, 0.f);
            if (gr < M)
                av = *(const float4*)(A + (size_t)gr * K + k0 + c4);
            As[c4 + 0][r] = av.x;
            As[c4 + 1][r] = av.y;
            As[c4 + 2][r] = av.z;
            As[c4 + 3][r] = av.w;
        }
        // B tile: 16 k-rows x 128 cols, direct float4
#pragma unroll
        for (int it = 0; it < 2; ++it) {
            int idx = tid + it * 256;          // 0..511
            int r   = idx >> 5;                // 0..15
            int c4  = (idx & 31) << 2;         // 0..124
            *(float4*)(&Bs[r][c4]) =
                *(const float4*)(B + (size_t)(k0 + r) * N + col0 + c4);
        }
        __syncthreads();

#pragma unroll
        for (int k = 0; k < 16; ++k) {
            const float4 a0 = *(const float4*)(&As[k][ty * 4]);
            const float4 a1 = *(const float4*)(&As[k][64 + ty * 4]);
            const float4 b0 = *(const float4*)(&Bs[k][tx * 4]);
            const float4 b1 = *(const float4*)(&Bs[k][64 + tx * 4]);
            const float av[2][4] = {{a0.x, a0.y, a0.z, a0.w},
                                    {a1.x, a1.y, a1.z, a1.w}};
            const float bv[2][4] = {{b0.x, b0.y, b0.z, b0.w},
                                    {b1.x, b1.y, b1.z, b1.w}};
#pragma unroll
            for (int g = 0; g < 2; ++g)
#pragma unroll
                for (int h = 0; h < 2; ++h)
#pragma unroll
                    for (int i = 0; i < 4; ++i)
#pragma unroll
                        for (int j = 0; j < 4; ++j)
                            acc[g][h][i][j] = fmaf(av[g][i], bv[h][j], acc[g][h][i][j]);
        }
        __syncthreads();
    }

    const float4 bias0 = *(const float4*)(bias + col0 + tx * 4);
    const float4 bias1 = *(const float4*)(bias + col0 + 64 + tx * 4);
    const float bb[2][4] = {{bias0.x, bias0.y, bias0.z, bias0.w},
                            {bias1.x, bias1.y, bias1.z, bias1.w}};
#pragma unroll
    for (int g = 0; g < 2; ++g)
#pragma unroll
        for (int i = 0; i < 4; ++i) {
            int gr = row0 + g * 64 + ty * 4 + i;
            if (gr < M) {
#pragma unroll
                for (int h = 0; h < 2; ++h) {
                    float4 o;
                    o.x = acc[g][h][i][0] + bb[h][0];
                    o.y = acc[g][h][i][1] + bb[h][1];
                    o.z = acc[g][h][i][2] + bb[h][2];
                    o.w = acc[g][h][i][3] + bb[h][3];
                    *(float4*)(C + (size_t)gr * N + col0 + h * 64 + tx * 4) = o;
                }
            }
        }
}

// ---------------- deformable sampling core --------------------------------
// grid = BS*NQ blocks, block = (32, 8): warp = one head, lane = channel d.
__global__ __launch_bounds__(256)
void msda_sample_kernel(const float* __restrict__ refp)
{
    __shared__ float4 st[NH][32][2];     // [head][point][{offs4, wts4}]

    const int bq   = blockIdx.x;          // b*NQ + q
    const int lane = threadIdx.x;         // 0..31
    const int h    = threadIdx.y;         // 0..7
    const int b    = bq >> 12;            // NQ = 4096

    // ---- softmax over the 32 attention logits of this (b,q,h) ----
    const float aval = g_attn[(size_t)bq * 256 + h * 32 + lane];
    float mx = aval;
#pragma unroll
    for (int s = 16; s; s >>= 1) mx = fmaxf(mx, __shfl_xor_sync(0xffffffffu, mx, s));
    const float e = __expf(aval - mx);
    float sm = e;
#pragma unroll
    for (int s = 16; s; s >>= 1) sm += __shfl_xor_sync(0xffffffffu, sm, s);
    const float aw = e / sm;              // lane j holds weight of point j

    // ---- per-lane (lane = point j) coordinate precompute ----
    {
        const int j  = lane;
        const int lv = j >> 3;
        const int Wl = cWL[lv], Hl = cHL[lv];

        const float2 o2 = *(const float2*)(g_off + (size_t)bq * 512 + h * 64 + j * 2);
        const float rx = refp[(size_t)bq * 8 + lv * 2];
        const float ry = refp[(size_t)bq * 8 + lv * 2 + 1];

        // mirror reference arithmetic: loc = ref + off/W; x = (2*loc)*(W/2) - 0.5
        const float locx = rx + o2.x * cIW[lv];
        const float locy = ry + o2.y * cIH[lv];
        const float gx = 2.f * locx - 1.f;
        const float gy = 2.f * locy - 1.f;
        const float x = (gx + 1.f) * ((float)Wl * 0.5f) - 0.5f;
        const float y = (gy + 1.f) * ((float)Hl * 0.5f) - 0.5f;

        const float xf = floorf(x), yf = floorf(y);
        const float wx = x - xf,    wy = y - yf;
        const int x0 = (int)xf, y0 = (int)yf;
        const int x1 = x0 + 1,  y1 = y0 + 1;

        const bool vx0 = (x0 >= 0) && (x0 < Wl);
        const bool vx1 = (x1 >= 0) && (x1 < Wl);
        const bool vy0 = (y0 >= 0) && (y0 < Hl);
        const bool vy1 = (y1 >= 0) && (y1 < Hl);

        const int xA = min(max(x0, 0), Wl - 1);
        const int xB = min(max(x1, 0), Wl - 1);
        const int yA = min(max(y0, 0), Hl - 1);
        const int yB = min(max(y1, 0), Hl - 1);

        // byte offsets into g_v row space (1024 B per spatial location)
        const int base = cST[lv];
        const int off00 = (base + yA * Wl + xA) << 10;
        const int off10 = (base + yA * Wl + xB) << 10;
        const int off01 = (base + yB * Wl + xA) << 10;
        const int off11 = (base + yB * Wl + xB) << 10;

        const float w00 = (vx0 && vy0) ? aw * (1.f - wx) * (1.f - wy) : 0.f;
        const float w10 = (vx1 && vy0) ? aw * wx         * (1.f - wy) : 0.f;
        const float w01 = (vx0 && vy1) ? aw * (1.f - wx) * wy         : 0.f;
        const float w11 = (vx1 && vy1) ? aw * wx         * wy         : 0.f;

        st[h][j][0] = make_float4(__int_as_float(off00), __int_as_float(off10),
                                  __int_as_float(off01), __int_as_float(off11));
        st[h][j][1] = make_float4(w00, w10, w01, w11);
    }
    __syncwarp();

    // ---- phase 2: lane = channel; accumulate 32 points ----
    const char* vb = (const char*)(g_v + (size_t)b * LTOT * EMB + h * 32 + lane);

    float acc = 0.f;
#pragma unroll 8
    for (int p = 0; p < 32; ++p) {
        const float4 o = st[h][p][0];
        const float4 w = st[h][p][1];
        const float v00 = *(const float*)(vb + __float_as_int(o.x));
        const float v10 = *(const float*)(vb + __float_as_int(o.y));
        const float v01 = *(const float*)(vb + __float_as_int(o.z));
        const float v11 = *(const float*)(vb + __float_as_int(o.w));
        acc = fmaf(w.x, v00, acc);
        acc = fmaf(w.y, v10, acc);
        acc = fmaf(w.z, v01, acc);
        acc = fmaf(w.w, v11, acc);
    }
    g_tmp[(size_t)bq * EMB + h * 32 + lane] = acc;
}

// ---------------- launch ---------------------------------------------------
extern "C" void kernel_launch(void* const* d_in, const int* in_sizes, int n_in,
                              void* d_out, int out_size)
{
    const float* query  = (const float*)d_in[0];
    const float* value  = (const float*)d_in[1];
    const float* refp   = (const float*)d_in[2];
    // d_in[3] = spatial_shapes (int32) — compile-time constants, unused
    const float* W_off  = (const float*)d_in[4];
    const float* b_off  = (const float*)d_in[5];
    const float* W_attn = (const float*)d_in[6];
    const float* b_attn = (const float*)d_in[7];
    const float* W_val  = (const float*)d_in[8];
    const float* b_val  = (const float*)d_in[9];
    const float* W_out  = (const float*)d_in[10];
    const float* b_out  = (const float*)d_in[11];
    float* out = (float*)d_out;

    float *gv, *goff, *gattn, *gtmp;
    cudaGetSymbolAddress((void**)&gv,    g_v);
    cudaGetSymbolAddress((void**)&goff,  g_off);
    cudaGetSymbolAddress((void**)&gattn, g_attn);
    cudaGetSymbolAddress((void**)&gtmp,  g_tmp);

    dim3 blk(256);

    // 1) value projection: [117360,256] @ [256,256] + b_val -> g_v
    gemm_bias_kernel<<<dim3(EMB / 128, (MV + 127) / 128), blk>>>(
        value, W_val, b_val, gv, MV, EMB, EMB);

    // 2) offsets: [24576,256] @ [256,512] + b_off -> g_off
    gemm_bias_kernel<<<dim3(512 / 128, MQ / 128), blk>>>(
        query, W_off, b_off, goff, MQ, 512, EMB);

    // 3) attention logits: [24576,256] @ [256,256] + b_attn -> g_attn
    gemm_bias_kernel<<<dim3(EMB / 128, MQ / 128), blk>>>(
        query, W_attn, b_attn, gattn, MQ, EMB, EMB);

    // 4) softmax + bilinear sampling -> g_tmp
    msda_sample_kernel<<<MQ, dim3(32, 8)>>>(refp);

    // 5) output projection: [24576,256] @ [256,256] + b_out -> d_out
    gemm_bias_kernel<<<dim3(EMB / 128, MQ / 128), blk>>>(
        gtmp, W_out, b_out, out, MQ, EMB, EMB);
}

// round 5
// speedup vs baseline: 2.4571x; 1.7265x over previous
#include <cuda_runtime.h>
#include <cuda_bf16.h>
#include <cstdint>

// ---------------- problem constants ----------------
#define BS   6
#define NQ   4096
#define EMB  256
#define NH   8
#define LTOT 19560            // 92*160 + 46*80 + 23*40 + 12*20
#define MQ   (BS * NQ)        // 24576
#define MV   (BS * LTOT)      // 117360
#define KDIM 256

// ---------------- scratch (device globals; no cudaMalloc allowed) ----------
__device__ float g_v   [(size_t)MV * EMB];
__device__ float g_off [(size_t)MQ * 512];
__device__ float g_attn[(size_t)MQ * 256];
__device__ float g_tmp [(size_t)MQ * EMB];

// transposed + hi/lo split weights: rows = output col n, 256 k each
// layout: [val 256 | attn 256 | out 256 | off 512] = 1280 rows
#define WT_VAL  0
#define WT_ATTN 256
#define WT_OUT  512
#define WT_OFF  768
__device__ __align__(128) __nv_bfloat16 g_wt_hi[1280 * 256];
__device__ __align__(128) __nv_bfloat16 g_wt_lo[1280 * 256];

__constant__ int   cHL[4] = {92, 46, 23, 12};
__constant__ int   cWL[4] = {160, 80, 40, 20};
__constant__ int   cST[4] = {0, 14720, 18400, 19320};
__constant__ float cIW[4] = {1.f/160.f, 1.f/80.f, 1.f/40.f, 1.f/20.f};
__constant__ float cIH[4] = {1.f/92.f,  1.f/46.f, 1.f/23.f, 1.f/12.f};

// ---------------- helpers ---------------------------------------------------
__device__ __forceinline__ uint32_t smem_u32(const void* p) {
    uint32_t a;
    asm("{ .reg .u64 t; cvta.to.shared.u64 t, %1; cvt.u32.u64 %0, t; }"
        : "=r"(a) : "l"(p));
    return a;
}
__device__ __forceinline__ void ldsm_x4(uint32_t* r, uint32_t addr) {
    asm volatile("ldmatrix.sync.aligned.m8n8.x4.shared.b16 {%0,%1,%2,%3}, [%4];"
                 : "=r"(r[0]), "=r"(r[1]), "=r"(r[2]), "=r"(r[3]) : "r"(addr));
}
__device__ __forceinline__ void mma_bf16(float* c, const uint32_t* a,
                                         const uint32_t* b) {
    asm volatile(
        "mma.sync.aligned.m16n8k16.row.col.f32.bf16.bf16.f32 "
        "{%0,%1,%2,%3}, {%4,%5,%6,%7}, {%8,%9}, {%0,%1,%2,%3};"
        : "+f"(c[0]), "+f"(c[1]), "+f"(c[2]), "+f"(c[3])
        : "r"(a[0]), "r"(a[1]), "r"(a[2]), "r"(a[3]), "r"(b[0]), "r"(b[1]));
}

// ---------------- weight prep: transpose + bf16 hi/lo split ---------------
__global__ void prep_weights(const float* __restrict__ Wv,
                             const float* __restrict__ Wa,
                             const float* __restrict__ Wo,
                             const float* __restrict__ Wf)
{
    const int n = blockIdx.x;       // 0..1279 transposed row
    const int k = threadIdx.x;      // 0..255
    const float* W; int N, row;
    if (n < 256)      { W = Wv; N = 256; row = n;       }
    else if (n < 512) { W = Wa; N = 256; row = n - 256; }
    else if (n < 768) { W = Wo; N = 256; row = n - 512; }
    else              { W = Wf; N = 512; row = n - 768; }
    const float w = W[(size_t)k * N + row];
    const __nv_bfloat16 h = __float2bfloat16(w);
    g_wt_hi[(size_t)n * 256 + k] = h;
    g_wt_lo[(size_t)n * 256 + k] = __float2bfloat16(w - __bfloat162float(h));
}

// ---------------- HMMA bf16x3 GEMM: C = A(Mx256) * Bt(Nx256)^T + bias ------
// tile 128x128, kb=64, 8 warps (4x2), warp tile 32x64, smem rows padded to
// 72 bf16 (144B) for conflict-free ldmatrix.
#define ROWB 144                    // bytes per smem row (64 bf16 + 8 pad)
#define SM_AHI 0
#define SM_ALO (128 * ROWB)
#define SM_BHI (2 * 128 * ROWB)
#define SM_BLO (3 * 128 * ROWB)
#define SMEM_DYN (4 * 128 * ROWB)   // 73728 B

__global__ __launch_bounds__(256, 2)
void gemm_tc_kernel(const float* __restrict__ A,
                    const __nv_bfloat16* __restrict__ BtHi,
                    const __nv_bfloat16* __restrict__ BtLo,
                    const float* __restrict__ bias,
                    float* __restrict__ C, int M, int N)
{
    extern __shared__ __align__(16) char sp[];
    const uint32_t s0 = smem_u32(sp);

    const int tid  = threadIdx.x;
    const int wid  = tid >> 5;
    const int lane = tid & 31;
    const int wm   = wid >> 1;           // 0..3 -> 32 rows each
    const int wn   = wid & 1;            // 0..1 -> 64 cols each
    const int row0 = blockIdx.y * 128;
    const int col0 = blockIdx.x * 128;

    // ldmatrix lane-address components
    const int lrA = (lane & 7) + ((lane >> 3) & 1) * 8;   // m within tile
    const int lkA = (lane >> 4) * 8;                      // k within tile
    const int lrB = (lane & 7) + (lane >> 4) * 8;         // n within tile-pair
    const int lkB = ((lane >> 3) & 1) * 8;                // k within tile

    float acc[2][8][4];
#pragma unroll
    for (int mt = 0; mt < 2; ++mt)
#pragma unroll
        for (int nt = 0; nt < 8; ++nt)
#pragma unroll
            for (int i = 0; i < 4; ++i) acc[mt][nt][i] = 0.f;

    for (int kb = 0; kb < 4; ++kb) {
        // ---- A tile: 128 rows x 64 k fp32 -> hi/lo bf16, padded rows ----
#pragma unroll
        for (int it = 0; it < 4; ++it) {
            const int idx = it * 256 + tid;      // 0..1023
            const int row = idx >> 3;            // 0..127
            const int seg = idx & 7;             // 8 floats each
            const int gr  = row0 + row;
            float4 fa = make_float4(0.f,0.f,0.f,0.f), fb = fa;
            if (gr < M) {
                const float* Ab = A + (size_t)gr * KDIM + kb * 64 + seg * 8;
                fa = *(const float4*)Ab;
                fb = *(const float4*)(Ab + 4);
            }
            const float f[8] = {fa.x, fa.y, fa.z, fa.w, fb.x, fb.y, fb.z, fb.w};
            uint32_t hi[4], lo[4];
#pragma unroll
            for (int i = 0; i < 4; ++i) {
                const float a0 = f[2*i], a1 = f[2*i+1];
                __nv_bfloat162 h2 = __floats2bfloat162_rn(a0, a1);
                const float r0 = a0 - __bfloat162float(h2.x);
                const float r1 = a1 - __bfloat162float(h2.y);
                __nv_bfloat162 l2 = __floats2bfloat162_rn(r0, r1);
                hi[i] = *reinterpret_cast<uint32_t*>(&h2);
                lo[i] = *reinterpret_cast<uint32_t*>(&l2);
            }
            const int off = row * ROWB + seg * 16;
            *(uint4*)(sp + SM_AHI + off) = make_uint4(hi[0], hi[1], hi[2], hi[3]);
            *(uint4*)(sp + SM_ALO + off) = make_uint4(lo[0], lo[1], lo[2], lo[3]);
        }
        // ---- B tile: 128 n-rows x 64 k bf16 (pre-split) ----
#pragma unroll
        for (int it = 0; it < 4; ++it) {
            const int idx = it * 256 + tid;
            const int row = idx >> 3;
            const int seg = idx & 7;
            const size_t gsrc = (size_t)(col0 + row) * KDIM + kb * 64 + seg * 8;
            const int off = row * ROWB + seg * 16;
            *(uint4*)(sp + SM_BHI + off) = *(const uint4*)(BtHi + gsrc);
            *(uint4*)(sp + SM_BLO + off) = *(const uint4*)(BtLo + gsrc);
        }
        __syncthreads();

        // ---- 4 k-steps of 16 ----
#pragma unroll
        for (int ks = 0; ks < 4; ++ks) {
            const int k0 = ks * 16;
            uint32_t ahi[2][4], alo[2][4];
#pragma unroll
            for (int mt = 0; mt < 2; ++mt) {
                const int m = wm * 32 + mt * 16 + lrA;
                const uint32_t aoff = (uint32_t)(m * ROWB + (k0 + lkA) * 2);
                ldsm_x4(ahi[mt], s0 + SM_AHI + aoff);
                ldsm_x4(alo[mt], s0 + SM_ALO + aoff);
            }
#pragma unroll
            for (int np = 0; np < 4; ++np) {     // n-tile pairs
                const int n = wn * 64 + np * 16 + lrB;
                const uint32_t boff = (uint32_t)(n * ROWB + (k0 + lkB) * 2);
                uint32_t bh[4], bl[4];
                ldsm_x4(bh, s0 + SM_BHI + boff);
                ldsm_x4(bl, s0 + SM_BLO + boff);
#pragma unroll
                for (int mt = 0; mt < 2; ++mt) {
#pragma unroll
                    for (int h2 = 0; h2 < 2; ++h2) {
                        float* c = acc[mt][np * 2 + h2];
                        mma_bf16(c, ahi[mt], bh + h2 * 2);
                        mma_bf16(c, ahi[mt], bl + h2 * 2);
                        mma_bf16(c, alo[mt], bh + h2 * 2);
                    }
                }
            }
        }
        __syncthreads();
    }

    // ---- epilogue: direct v2 stores + bias ----
    const int q  = lane >> 2;            // 0..7
    const int n2 = (lane & 3) * 2;
#pragma unroll
    for (int mt = 0; mt < 2; ++mt) {
        const int mbase = row0 + wm * 32 + mt * 16 + q;
#pragma unroll
        for (int nt = 0; nt < 8; ++nt) {
            const int gc = col0 + wn * 64 + nt * 8 + n2;
            const float bx = bias[gc], by = bias[gc + 1];
            const float* c = acc[mt][nt];
            if (mbase < M)
                *(float2*)(C + (size_t)mbase * N + gc) =
                    make_float2(c[0] + bx, c[1] + by);
            if (mbase + 8 < M)
                *(float2*)(C + (size_t)(mbase + 8) * N + gc) =
                    make_float2(c[2] + bx, c[3] + by);
        }
    }
}

// ---------------- deformable sampling core --------------------------------
__global__ __launch_bounds__(256)
void msda_sample_kernel(const float* __restrict__ refp)
{
    __shared__ float4 st[NH][32][2];

    const int bq   = blockIdx.x;
    const int lane = threadIdx.x;
    const int h    = threadIdx.y;
    const int b    = bq >> 12;

    const float aval = g_attn[(size_t)bq * 256 + h * 32 + lane];
    float mx = aval;
#pragma unroll
    for (int s = 16; s; s >>= 1) mx = fmaxf(mx, __shfl_xor_sync(0xffffffffu, mx, s));
    const float e = __expf(aval - mx);
    float sm = e;
#pragma unroll
    for (int s = 16; s; s >>= 1) sm += __shfl_xor_sync(0xffffffffu, sm, s);
    const float aw = e / sm;

    {
        const int j  = lane;
        const int lv = j >> 3;
        const int Wl = cWL[lv], Hl = cHL[lv];

        const float2 o2 = *(const float2*)(g_off + (size_t)bq * 512 + h * 64 + j * 2);
        const float rx = refp[(size_t)bq * 8 + lv * 2];
        const float ry = refp[(size_t)bq * 8 + lv * 2 + 1];

        const float locx = rx + o2.x * cIW[lv];
        const float locy = ry + o2.y * cIH[lv];
        const float gx = 2.f * locx - 1.f;
        const float gy = 2.f * locy - 1.f;
        const float x = (gx + 1.f) * ((float)Wl * 0.5f) - 0.5f;
        const float y = (gy + 1.f) * ((float)Hl * 0.5f) - 0.5f;

        const float xf = floorf(x), yf = floorf(y);
        const float wx = x - xf,    wy = y - yf;
        const int x0 = (int)xf, y0 = (int)yf;
        const int x1 = x0 + 1,  y1 = y0 + 1;

        const bool vx0 = (x0 >= 0) && (x0 < Wl);
        const bool vx1 = (x1 >= 0) && (x1 < Wl);
        const bool vy0 = (y0 >= 0) && (y0 < Hl);
        const bool vy1 = (y1 >= 0) && (y1 < Hl);

        const int xA = min(max(x0, 0), Wl - 1);
        const int xB = min(max(x1, 0), Wl - 1);
        const int yA = min(max(y0, 0), Hl - 1);
        const int yB = min(max(y1, 0), Hl - 1);

        const int base = cST[lv];
        const int off00 = (base + yA * Wl + xA) << 10;
        const int off10 = (base + yA * Wl + xB) << 10;
        const int off01 = (base + yB * Wl + xA) << 10;
        const int off11 = (base + yB * Wl + xB) << 10;

        const float w00 = (vx0 && vy0) ? aw * (1.f - wx) * (1.f - wy) : 0.f;
        const float w10 = (vx1 && vy0) ? aw * wx         * (1.f - wy) : 0.f;
        const float w01 = (vx0 && vy1) ? aw * (1.f - wx) * wy         : 0.f;
        const float w11 = (vx1 && vy1) ? aw * wx         * wy         : 0.f;

        st[h][j][0] = make_float4(__int_as_float(off00), __int_as_float(off10),
                                  __int_as_float(off01), __int_as_float(off11));
        st[h][j][1] = make_float4(w00, w10, w01, w11);
    }
    __syncwarp();

    const char* vb = (const char*)(g_v + (size_t)b * LTOT * EMB + h * 32 + lane);

    float acc = 0.f;
#pragma unroll 8
    for (int p = 0; p < 32; ++p) {
        const float4 o = st[h][p][0];
        const float4 w = st[h][p][1];
        const float v00 = *(const float*)(vb + __float_as_int(o.x));
        const float v10 = *(const float*)(vb + __float_as_int(o.y));
        const float v01 = *(const float*)(vb + __float_as_int(o.z));
        const float v11 = *(const float*)(vb + __float_as_int(o.w));
        acc = fmaf(w.x, v00, acc);
        acc = fmaf(w.y, v10, acc);
        acc = fmaf(w.z, v01, acc);
        acc = fmaf(w.w, v11, acc);
    }
    g_tmp[(size_t)bq * EMB + h * 32 + lane] = acc;
}

// ---------------- launch ---------------------------------------------------
extern "C" void kernel_launch(void* const* d_in, const int* in_sizes, int n_in,
                              void* d_out, int out_size)
{
    const float* query  = (const float*)d_in[0];
    const float* value  = (const float*)d_in[1];
    const float* refp   = (const float*)d_in[2];
    const float* W_off  = (const float*)d_in[4];
    const float* b_off  = (const float*)d_in[5];
    const float* W_attn = (const float*)d_in[6];
    const float* b_attn = (const float*)d_in[7];
    const float* W_val  = (const float*)d_in[8];
    const float* b_val  = (const float*)d_in[9];
    const float* W_out  = (const float*)d_in[10];
    const float* b_out  = (const float*)d_in[11];
    float* out = (float*)d_out;

    float *gv, *goff, *gattn, *gtmp;
    __nv_bfloat16 *wth, *wtl;
    cudaGetSymbolAddress((void**)&gv,    g_v);
    cudaGetSymbolAddress((void**)&goff,  g_off);
    cudaGetSymbolAddress((void**)&gattn, g_attn);
    cudaGetSymbolAddress((void**)&gtmp,  g_tmp);
    cudaGetSymbolAddress((void**)&wth,   g_wt_hi);
    cudaGetSymbolAddress((void**)&wtl,   g_wt_lo);

    cudaFuncSetAttribute(gemm_tc_kernel,
                         cudaFuncAttributeMaxDynamicSharedMemorySize, SMEM_DYN);

    // 0) weight transpose + bf16 hi/lo split
    prep_weights<<<1280, 256>>>(W_val, W_attn, W_out, W_off);

    // 1) value projection -> g_v
    gemm_tc_kernel<<<dim3(2, (MV + 127) / 128), 256, SMEM_DYN>>>(
        value, wth + (size_t)WT_VAL * 256, wtl + (size_t)WT_VAL * 256,
        b_val, gv, MV, 256);

    // 2) offsets -> g_off
    gemm_tc_kernel<<<dim3(4, MQ / 128), 256, SMEM_DYN>>>(
        query, wth + (size_t)WT_OFF * 256, wtl + (size_t)WT_OFF * 256,
        b_off, goff, MQ, 512);

    // 3) attention logits -> g_attn
    gemm_tc_kernel<<<dim3(2, MQ / 128), 256, SMEM_DYN>>>(
        query, wth + (size_t)WT_ATTN * 256, wtl + (size_t)WT_ATTN * 256,
        b_attn, gattn, MQ, 256);

    // 4) softmax + bilinear sampling -> g_tmp
    msda_sample_kernel<<<MQ, dim3(32, 8)>>>(refp);

    // 5) output projection -> d_out
    gemm_tc_kernel<<<dim3(2, MQ / 128), 256, SMEM_DYN>>>(
        gtmp, wth + (size_t)WT_OUT * 256, wtl + (size_t)WT_OUT * 256,
        b_out, out, MQ, 256);
}

// round 6
// speedup vs baseline: 2.5437x; 1.0353x over previous
#include <cuda_runtime.h>
#include <cuda_bf16.h>
#include <cstdint>

// ---------------- problem constants ----------------
#define BS   6
#define NQ   4096
#define EMB  256
#define NH   8
#define LTOT 19560            // 92*160 + 46*80 + 23*40 + 12*20
#define MQ   (BS * NQ)        // 24576
#define MV   (BS * LTOT)      // 117360
#define KDIM 256

// ---------------- scratch (device globals; no cudaMalloc allowed) ----------
__device__ float g_v  [(size_t)MV * EMB];
__device__ float g_qo [(size_t)MQ * 768];    // [attn 256 | off 512] per row
__device__ float g_tmp[(size_t)MQ * EMB];
__device__ float g_bqo[768];                 // fused bias [b_attn | b_off]

// transposed + hi/lo split weights, rows = output col n, 256 k each
// layout: [val 256 | attn 256 | off 512 | out 256] = 1280 rows
#define WT_VAL  0
#define WT_QRY  256          // attn(256) + off(512) fused = 768 rows
#define WT_OUT  1024
__device__ __align__(128) __nv_bfloat16 g_wt_hi[1280 * 256];
__device__ __align__(128) __nv_bfloat16 g_wt_lo[1280 * 256];

__constant__ int   cHL[4] = {92, 46, 23, 12};
__constant__ int   cWL[4] = {160, 80, 40, 20};
__constant__ int   cST[4] = {0, 14720, 18400, 19320};
__constant__ float cIW[4] = {1.f/160.f, 1.f/80.f, 1.f/40.f, 1.f/20.f};
__constant__ float cIH[4] = {1.f/92.f,  1.f/46.f, 1.f/23.f, 1.f/12.f};

// ---------------- helpers ---------------------------------------------------
__device__ __forceinline__ uint32_t smem_u32(const void* p) {
    uint32_t a;
    asm("{ .reg .u64 t; cvta.to.shared.u64 t, %1; cvt.u32.u64 %0, t; }"
        : "=r"(a) : "l"(p));
    return a;
}
__device__ __forceinline__ void ldsm_x4(uint32_t* r, uint32_t addr) {
    asm volatile("ldmatrix.sync.aligned.m8n8.x4.shared.b16 {%0,%1,%2,%3}, [%4];"
                 : "=r"(r[0]), "=r"(r[1]), "=r"(r[2]), "=r"(r[3]) : "r"(addr));
}
__device__ __forceinline__ void mma_bf16(float* c, const uint32_t* a,
                                         const uint32_t* b) {
    asm volatile(
        "mma.sync.aligned.m16n8k16.row.col.f32.bf16.bf16.f32 "
        "{%0,%1,%2,%3}, {%4,%5,%6,%7}, {%8,%9}, {%0,%1,%2,%3};"
        : "+f"(c[0]), "+f"(c[1]), "+f"(c[2]), "+f"(c[3])
        : "r"(a[0]), "r"(a[1]), "r"(a[2]), "r"(a[3]), "r"(b[0]), "r"(b[1]));
}
__device__ __forceinline__ void cp16(uint32_t dst, const void* src, uint32_t sz) {
    asm volatile("cp.async.cg.shared.global [%0], [%1], 16, %2;"
                 :: "r"(dst), "l"(src), "r"(sz) : "memory");
}
#define CP_COMMIT() asm volatile("cp.async.commit_group;" ::: "memory")
#define CP_WAIT(n)  asm volatile("cp.async.wait_group " #n ";" ::: "memory")

// ---------------- weight prep: transpose + bf16 hi/lo split ---------------
__global__ void prep_weights(const float* __restrict__ Wv,
                             const float* __restrict__ Wa,
                             const float* __restrict__ Wf,
                             const float* __restrict__ Wo,
                             const float* __restrict__ ba,
                             const float* __restrict__ bf)
{
    const int n = blockIdx.x;       // 0..1279 transposed row
    const int k = threadIdx.x;      // 0..255
    if (n == 0) g_bqo[k]       = ba[k];
    if (n == 1) g_bqo[256 + k] = bf[k];
    if (n == 2) g_bqo[512 + k] = bf[256 + k];
    const float* W; int N, row;
    if (n < 256)       { W = Wv; N = 256; row = n;        }
    else if (n < 512)  { W = Wa; N = 256; row = n - 256;  }
    else if (n < 1024) { W = Wf; N = 512; row = n - 512;  }
    else               { W = Wo; N = 256; row = n - 1024; }
    const float w = W[(size_t)k * N + row];
    const __nv_bfloat16 h = __float2bfloat16(w);
    g_wt_hi[(size_t)n * 256 + k] = h;
    g_wt_lo[(size_t)n * 256 + k] = __float2bfloat16(w - __bfloat162float(h));
}

// ---------------- HMMA bf16x3 GEMM, cp.async 2-stage pipeline --------------
// tile 64x128, kb=32, 128 threads (4 warps 2x2), warp tile 32x64.
// smem/stage: A fp32 64x160B | Bhi 128x80B | Blo 128x80B
#define AROW 160
#define BROW 80
#define S_A   0
#define S_BHI 10240
#define S_BLO 20480
#define STG   30720
#define SMEM_DYN (2 * STG)          // 61440 B

__global__ __launch_bounds__(128, 3)
void gemm_tc_kernel(const float* __restrict__ A,
                    const __nv_bfloat16* __restrict__ BtHi,
                    const __nv_bfloat16* __restrict__ BtLo,
                    const float* __restrict__ bias,
                    float* __restrict__ C, int M, int N)
{
    extern __shared__ __align__(16) char sp[];
    const uint32_t s0 = smem_u32(sp);

    const int tid  = threadIdx.x;
    const int wid  = tid >> 5;
    const int lane = tid & 31;
    const int wm   = wid >> 1;           // 0..1 -> 32 rows each
    const int wn   = wid & 1;            // 0..1 -> 64 cols each
    const int row0 = blockIdx.y * 64;
    const int col0 = blockIdx.x * 128;

    const int q  = lane >> 2;            // 0..7
    const int t2 = (lane & 3) * 2;
    const int lrB = (lane & 7) + (lane >> 4) * 8;
    const int lkB = ((lane >> 3) & 1) * 8;

    float acc[2][8][4];
#pragma unroll
    for (int mt = 0; mt < 2; ++mt)
#pragma unroll
        for (int nt = 0; nt < 8; ++nt)
#pragma unroll
            for (int i = 0; i < 4; ++i) acc[mt][nt][i] = 0.f;

    // ---- async loader for one kb block into stage st ----
    auto load_kb = [&](int kb, int st) {
        const uint32_t sb = s0 + st * STG;
        // A: 64 rows x 32 floats (128B data), 512 chunks, 4/thread
#pragma unroll
        for (int it = 0; it < 4; ++it) {
            const int chunk = it * 128 + tid;
            const int row = chunk >> 3, c = chunk & 7;
            const int gr  = row0 + row;
            const int vr  = (gr < M) ? gr : 0;
            cp16(sb + S_A + row * AROW + c * 16,
                 A + (size_t)vr * KDIM + kb * 32 + c * 4,
                 (gr < M) ? 16u : 0u);
        }
        // B hi/lo: 128 rows x 32 bf16 (64B data), 1024 chunks, 8/thread
#pragma unroll
        for (int it = 0; it < 8; ++it) {
            const int chunk = it * 128 + tid;
            const int half = chunk >> 9;
            const int r = (chunk >> 2) & 127, c = chunk & 3;
            const __nv_bfloat16* src = (half ? BtLo : BtHi)
                                     + (size_t)(col0 + r) * KDIM + kb * 32 + c * 8;
            cp16(sb + (half ? S_BLO : S_BHI) + r * BROW + c * 16, src, 16u);
        }
    };

    load_kb(0, 0);
    CP_COMMIT();

    int s = 0;
    for (int kb = 0; kb < 8; ++kb) {
        if (kb < 7) {
            load_kb(kb + 1, s ^ 1);
            CP_COMMIT();
            CP_WAIT(1);
        } else {
            CP_WAIT(0);
        }
        __syncthreads();

        const char*    spA = sp + s * STG + S_A;
        const uint32_t sbB = s0 + s * STG;

#pragma unroll
        for (int ks = 0; ks < 2; ++ks) {
            const int k0 = ks * 16;
            // ---- A fragments: fp32 LDS + on-the-fly hi/lo split ----
            uint32_t ahi[2][4], alo[2][4];
#pragma unroll
            for (int mt = 0; mt < 2; ++mt) {
                const int rb = wm * 32 + mt * 16 + q;
#pragma unroll
                for (int i = 0; i < 4; ++i) {
                    const int r = rb + (i & 1) * 8;
                    const int k = k0 + t2 + (i >> 1) * 8;
                    const float2 f = *(const float2*)(spA + r * AROW + k * 4);
                    __nv_bfloat162 h2 = __floats2bfloat162_rn(f.x, f.y);
                    const uint32_t h = *reinterpret_cast<uint32_t*>(&h2);
                    const float g0 = __uint_as_float(h << 16);
                    const float g1 = __uint_as_float(h & 0xFFFF0000u);
                    __nv_bfloat162 l2 = __floats2bfloat162_rn(f.x - g0, f.y - g1);
                    ahi[mt][i] = h;
                    alo[mt][i] = *reinterpret_cast<uint32_t*>(&l2);
                }
            }
#pragma unroll
            for (int np = 0; np < 4; ++np) {
                const int n = wn * 64 + np * 16 + lrB;
                const uint32_t boff = (uint32_t)(n * BROW + (k0 + lkB) * 2);
                uint32_t bh[4], bl[4];
                ldsm_x4(bh, sbB + S_BHI + boff);
                ldsm_x4(bl, sbB + S_BLO + boff);
#pragma unroll
                for (int mt = 0; mt < 2; ++mt) {
#pragma unroll
                    for (int h2 = 0; h2 < 2; ++h2) {
                        float* c = acc[mt][np * 2 + h2];
                        mma_bf16(c, ahi[mt], bh + h2 * 2);
                        mma_bf16(c, ahi[mt], bl + h2 * 2);
                        mma_bf16(c, alo[mt], bh + h2 * 2);
                    }
                }
            }
        }
        __syncthreads();
        s ^= 1;
    }

    // ---- epilogue: direct v2 stores + bias ----
    const int n2 = (lane & 3) * 2;
#pragma unroll
    for (int mt = 0; mt < 2; ++mt) {
        const int mbase = row0 + wm * 32 + mt * 16 + q;
#pragma unroll
        for (int nt = 0; nt < 8; ++nt) {
            const int gc = col0 + wn * 64 + nt * 8 + n2;
            const float bx = bias[gc], by = bias[gc + 1];
            const float* c = acc[mt][nt];
            if (mbase < M)
                *(float2*)(C + (size_t)mbase * N + gc) =
                    make_float2(c[0] + bx, c[1] + by);
            if (mbase + 8 < M)
                *(float2*)(C + (size_t)(mbase + 8) * N + gc) =
                    make_float2(c[2] + bx, c[3] + by);
        }
    }
}

// ---------------- deformable sampling core --------------------------------
__global__ __launch_bounds__(256)
void msda_sample_kernel(const float* __restrict__ refp)
{
    __shared__ float4 st[NH][32][2];

    const int bq   = blockIdx.x;
    const int lane = threadIdx.x;
    const int h    = threadIdx.y;
    const int b    = bq >> 12;

    const float aval = g_qo[(size_t)bq * 768 + h * 32 + lane];
    float mx = aval;
#pragma unroll
    for (int s = 16; s; s >>= 1) mx = fmaxf(mx, __shfl_xor_sync(0xffffffffu, mx, s));
    const float e = __expf(aval - mx);
    float sm = e;
#pragma unroll
    for (int s = 16; s; s >>= 1) sm += __shfl_xor_sync(0xffffffffu, sm, s);
    const float aw = e / sm;

    {
        const int j  = lane;
        const int lv = j >> 3;
        const int Wl = cWL[lv], Hl = cHL[lv];

        const float2 o2 = *(const float2*)(g_qo + (size_t)bq * 768 + 256
                                           + h * 64 + j * 2);
        const float rx = refp[(size_t)bq * 8 + lv * 2];
        const float ry = refp[(size_t)bq * 8 + lv * 2 + 1];

        const float locx = rx + o2.x * cIW[lv];
        const float locy = ry + o2.y * cIH[lv];
        const float gx = 2.f * locx - 1.f;
        const float gy = 2.f * locy - 1.f;
        const float x = (gx + 1.f) * ((float)Wl * 0.5f) - 0.5f;
        const float y = (gy + 1.f) * ((float)Hl * 0.5f) - 0.5f;

        const float xf = floorf(x), yf = floorf(y);
        const float wx = x - xf,    wy = y - yf;
        const int x0 = (int)xf, y0 = (int)yf;
        const int x1 = x0 + 1,  y1 = y0 + 1;

        const bool vx0 = (x0 >= 0) && (x0 < Wl);
        const bool vx1 = (x1 >= 0) && (x1 < Wl);
        const bool vy0 = (y0 >= 0) && (y0 < Hl);
        const bool vy1 = (y1 >= 0) && (y1 < Hl);

        const int xA = min(max(x0, 0), Wl - 1);
        const int xB = min(max(x1, 0), Wl - 1);
        const int yA = min(max(y0, 0), Hl - 1);
        const int yB = min(max(y1, 0), Hl - 1);

        const int base = cST[lv];
        const int off00 = (base + yA * Wl + xA) << 10;
        const int off10 = (base + yA * Wl + xB) << 10;
        const int off01 = (base + yB * Wl + xA) << 10;
        const int off11 = (base + yB * Wl + xB) << 10;

        const float w00 = (vx0 && vy0) ? aw * (1.f - wx) * (1.f - wy) : 0.f;
        const float w10 = (vx1 && vy0) ? aw * wx         * (1.f - wy) : 0.f;
        const float w01 = (vx0 && vy1) ? aw * (1.f - wx) * wy         : 0.f;
        const float w11 = (vx1 && vy1) ? aw * wx         * wy         : 0.f;

        st[h][j][0] = make_float4(__int_as_float(off00), __int_as_float(off10),
                                  __int_as_float(off01), __int_as_float(off11));
        st[h][j][1] = make_float4(w00, w10, w01, w11);
    }
    __syncwarp();

    const char* vb = (const char*)(g_v + (size_t)b * LTOT * EMB + h * 32 + lane);

    float acc = 0.f;
#pragma unroll 8
    for (int p = 0; p < 32; ++p) {
        const float4 o = st[h][p][0];
        const float4 w = st[h][p][1];
        const float v00 = *(const float*)(vb + __float_as_int(o.x));
        const float v10 = *(const float*)(vb + __float_as_int(o.y));
        const float v01 = *(const float*)(vb + __float_as_int(o.z));
        const float v11 = *(const float*)(vb + __float_as_int(o.w));
        acc = fmaf(w.x, v00, acc);
        acc = fmaf(w.y, v10, acc);
        acc = fmaf(w.z, v01, acc);
        acc = fmaf(w.w, v11, acc);
    }
    g_tmp[(size_t)bq * EMB + h * 32 + lane] = acc;
}

// ---------------- launch ---------------------------------------------------
extern "C" void kernel_launch(void* const* d_in, const int* in_sizes, int n_in,
                              void* d_out, int out_size)
{
    const float* query  = (const float*)d_in[0];
    const float* value  = (const float*)d_in[1];
    const float* refp   = (const float*)d_in[2];
    const float* W_off  = (const float*)d_in[4];
    const float* b_off  = (const float*)d_in[5];
    const float* W_attn = (const float*)d_in[6];
    const float* b_attn = (const float*)d_in[7];
    const float* W_val  = (const float*)d_in[8];
    const float* b_val  = (const float*)d_in[9];
    const float* W_out  = (const float*)d_in[10];
    const float* b_out  = (const float*)d_in[11];
    float* out = (float*)d_out;

    float *gv, *gqo, *gtmp, *gbqo;
    __nv_bfloat16 *wth, *wtl;
    cudaGetSymbolAddress((void**)&gv,   g_v);
    cudaGetSymbolAddress((void**)&gqo,  g_qo);
    cudaGetSymbolAddress((void**)&gtmp, g_tmp);
    cudaGetSymbolAddress((void**)&gbqo, g_bqo);
    cudaGetSymbolAddress((void**)&wth,  g_wt_hi);
    cudaGetSymbolAddress((void**)&wtl,  g_wt_lo);

    cudaFuncSetAttribute(gemm_tc_kernel,
                         cudaFuncAttributeMaxDynamicSharedMemorySize, SMEM_DYN);

    // 0) weight transpose + bf16 hi/lo split + fused bias
    prep_weights<<<1280, 256>>>(W_val, W_attn, W_off, W_out, b_attn, b_off);

    // 1) value projection -> g_v   [117360 x 256]
    gemm_tc_kernel<<<dim3(2, (MV + 63) / 64), 128, SMEM_DYN>>>(
        value, wth + (size_t)WT_VAL * 256, wtl + (size_t)WT_VAL * 256,
        b_val, gv, MV, 256);

    // 2) fused attn+off -> g_qo    [24576 x 768]
    gemm_tc_kernel<<<dim3(6, MQ / 64), 128, SMEM_DYN>>>(
        query, wth + (size_t)WT_QRY * 256, wtl + (size_t)WT_QRY * 256,
        gbqo, gqo, MQ, 768);

    // 3) softmax + bilinear sampling -> g_tmp
    msda_sample_kernel<<<MQ, dim3(32, 8)>>>(refp);

    // 4) output projection -> d_out
    gemm_tc_kernel<<<dim3(2, MQ / 64), 128, SMEM_DYN>>>(
        gtmp, wth + (size_t)WT_OUT * 256, wtl + (size_t)WT_OUT * 256,
        b_out, out, MQ, 256);
}

// round 7
// speedup vs baseline: 2.7872x; 1.0957x over previous
#include <cuda_runtime.h>
#include <cuda_bf16.h>
#include <cstdint>

// ---------------- problem constants ----------------
#define BS   6
#define NQ   4096
#define EMB  256
#define NH   8
#define LTOT 19560            // 92*160 + 46*80 + 23*40 + 12*20
#define MQ   (BS * NQ)        // 24576
#define MV   (BS * LTOT)      // 117360
#define KDIM 256

// ---------------- scratch (device globals; no cudaMalloc allowed) ----------
__device__ float g_v  [(size_t)MV * EMB];
__device__ float g_qo [(size_t)MQ * 768];    // [attn 256 | off 512] per row
__device__ float g_tmp[(size_t)MQ * EMB];
__device__ float g_bqo[768];                 // fused bias [b_attn | b_off]

// transposed + hi/lo split weights, rows = output col n, 256 k each
// layout: [val 256 | attn 256 | off 512 | out 256] = 1280 rows
#define WT_VAL  0
#define WT_QRY  256          // attn(256) + off(512) fused = 768 rows
#define WT_OUT  1024
__device__ __align__(128) __nv_bfloat16 g_wt_hi[1280 * 256];
__device__ __align__(128) __nv_bfloat16 g_wt_lo[1280 * 256];

__constant__ int   cHL[4] = {92, 46, 23, 12};
__constant__ int   cWL[4] = {160, 80, 40, 20};
__constant__ int   cST[4] = {0, 14720, 18400, 19320};
__constant__ float cIW[4] = {1.f/160.f, 1.f/80.f, 1.f/40.f, 1.f/20.f};
__constant__ float cIH[4] = {1.f/92.f,  1.f/46.f, 1.f/23.f, 1.f/12.f};

// ---------------- helpers ---------------------------------------------------
__device__ __forceinline__ uint32_t smem_u32(const void* p) {
    uint32_t a;
    asm("{ .reg .u64 t; cvta.to.shared.u64 t, %1; cvt.u32.u64 %0, t; }"
        : "=r"(a) : "l"(p));
    return a;
}
__device__ __forceinline__ void ldsm_x4(uint32_t* r, uint32_t addr) {
    asm volatile("ldmatrix.sync.aligned.m8n8.x4.shared.b16 {%0,%1,%2,%3}, [%4];"
                 : "=r"(r[0]), "=r"(r[1]), "=r"(r[2]), "=r"(r[3]) : "r"(addr));
}
__device__ __forceinline__ void mma_bf16(float* c, const uint32_t* a,
                                         const uint32_t* b) {
    asm volatile(
        "mma.sync.aligned.m16n8k16.row.col.f32.bf16.bf16.f32 "
        "{%0,%1,%2,%3}, {%4,%5,%6,%7}, {%8,%9}, {%0,%1,%2,%3};"
        : "+f"(c[0]), "+f"(c[1]), "+f"(c[2]), "+f"(c[3])
        : "r"(a[0]), "r"(a[1]), "r"(a[2]), "r"(a[3]), "r"(b[0]), "r"(b[1]));
}
__device__ __forceinline__ void cp16(uint32_t dst, const void* src, uint32_t sz) {
    asm volatile("cp.async.cg.shared.global [%0], [%1], 16, %2;"
                 :: "r"(dst), "l"(src), "r"(sz) : "memory");
}
#define CP_COMMIT() asm volatile("cp.async.commit_group;" ::: "memory")
#define CP_WAIT(n)  asm volatile("cp.async.wait_group " #n ";" ::: "memory")

// ---------------- weight prep: transpose + bf16 hi/lo split ---------------
__global__ void prep_weights(const float* __restrict__ Wv,
                             const float* __restrict__ Wa,
                             const float* __restrict__ Wf,
                             const float* __restrict__ Wo,
                             const float* __restrict__ ba,
                             const float* __restrict__ bf)
{
    const int n = blockIdx.x;       // 0..1279 transposed row
    const int k = threadIdx.x;      // 0..255
    if (n == 0) g_bqo[k]       = ba[k];
    if (n == 1) g_bqo[256 + k] = bf[k];
    if (n == 2) g_bqo[512 + k] = bf[256 + k];
    const float* W; int N, row;
    if (n < 256)       { W = Wv; N = 256; row = n;        }
    else if (n < 512)  { W = Wa; N = 256; row = n - 256;  }
    else if (n < 1024) { W = Wf; N = 512; row = n - 512;  }
    else               { W = Wo; N = 256; row = n - 1024; }
    const float w = W[(size_t)k * N + row];
    const __nv_bfloat16 h = __float2bfloat16(w);
    g_wt_hi[(size_t)n * 256 + k] = h;
    g_wt_lo[(size_t)n * 256 + k] = __float2bfloat16(w - __bfloat162float(h));
}

// ---------------- HMMA bf16x3 GEMM, cp.async 2-stage pipeline --------------
// tile 64x128, kb=32, 128 threads (4 warps 2x2), warp tile 32x64.
#define AROW 160
#define BROW 80
#define S_A   0
#define S_BHI 10240
#define S_BLO 20480
#define STG   30720
#define SMEM_DYN (2 * STG)          // 61440 B

__global__ __launch_bounds__(128, 3)
void gemm_tc_kernel(const float* __restrict__ A,
                    const __nv_bfloat16* __restrict__ BtHi,
                    const __nv_bfloat16* __restrict__ BtLo,
                    const float* __restrict__ bias,
                    float* __restrict__ C, int M, int N)
{
    extern __shared__ __align__(16) char sp[];
    const uint32_t s0 = smem_u32(sp);

    const int tid  = threadIdx.x;
    const int wid  = tid >> 5;
    const int lane = tid & 31;
    const int wm   = wid >> 1;
    const int wn   = wid & 1;
    const int row0 = blockIdx.y * 64;
    const int col0 = blockIdx.x * 128;

    const int q  = lane >> 2;
    const int t2 = (lane & 3) * 2;
    const int lrB = (lane & 7) + (lane >> 4) * 8;
    const int lkB = ((lane >> 3) & 1) * 8;

    float acc[2][8][4];
#pragma unroll
    for (int mt = 0; mt < 2; ++mt)
#pragma unroll
        for (int nt = 0; nt < 8; ++nt)
#pragma unroll
            for (int i = 0; i < 4; ++i) acc[mt][nt][i] = 0.f;

    auto load_kb = [&](int kb, int st) {
        const uint32_t sb = s0 + st * STG;
#pragma unroll
        for (int it = 0; it < 4; ++it) {
            const int chunk = it * 128 + tid;
            const int row = chunk >> 3, c = chunk & 7;
            const int gr  = row0 + row;
            const int vr  = (gr < M) ? gr : 0;
            cp16(sb + S_A + row * AROW + c * 16,
                 A + (size_t)vr * KDIM + kb * 32 + c * 4,
                 (gr < M) ? 16u : 0u);
        }
#pragma unroll
        for (int it = 0; it < 8; ++it) {
            const int chunk = it * 128 + tid;
            const int half = chunk >> 9;
            const int r = (chunk >> 2) & 127, c = chunk & 3;
            const __nv_bfloat16* src = (half ? BtLo : BtHi)
                                     + (size_t)(col0 + r) * KDIM + kb * 32 + c * 8;
            cp16(sb + (half ? S_BLO : S_BHI) + r * BROW + c * 16, src, 16u);
        }
    };

    load_kb(0, 0);
    CP_COMMIT();

    int s = 0;
    for (int kb = 0; kb < 8; ++kb) {
        if (kb < 7) {
            load_kb(kb + 1, s ^ 1);
            CP_COMMIT();
            CP_WAIT(1);
        } else {
            CP_WAIT(0);
        }
        __syncthreads();

        const char*    spA = sp + s * STG + S_A;
        const uint32_t sbB = s0 + s * STG;

#pragma unroll
        for (int ks = 0; ks < 2; ++ks) {
            const int k0 = ks * 16;
            uint32_t ahi[2][4], alo[2][4];
#pragma unroll
            for (int mt = 0; mt < 2; ++mt) {
                const int rb = wm * 32 + mt * 16 + q;
#pragma unroll
                for (int i = 0; i < 4; ++i) {
                    const int r = rb + (i & 1) * 8;
                    const int k = k0 + t2 + (i >> 1) * 8;
                    const float2 f = *(const float2*)(spA + r * AROW + k * 4);
                    __nv_bfloat162 h2 = __floats2bfloat162_rn(f.x, f.y);
                    const uint32_t h = *reinterpret_cast<uint32_t*>(&h2);
                    const float g0 = __uint_as_float(h << 16);
                    const float g1 = __uint_as_float(h & 0xFFFF0000u);
                    __nv_bfloat162 l2 = __floats2bfloat162_rn(f.x - g0, f.y - g1);
                    ahi[mt][i] = h;
                    alo[mt][i] = *reinterpret_cast<uint32_t*>(&l2);
                }
            }
#pragma unroll
            for (int np = 0; np < 4; ++np) {
                const int n = wn * 64 + np * 16 + lrB;
                const uint32_t boff = (uint32_t)(n * BROW + (k0 + lkB) * 2);
                uint32_t bh[4], bl[4];
                ldsm_x4(bh, sbB + S_BHI + boff);
                ldsm_x4(bl, sbB + S_BLO + boff);
#pragma unroll
                for (int mt = 0; mt < 2; ++mt) {
#pragma unroll
                    for (int h2 = 0; h2 < 2; ++h2) {
                        float* c = acc[mt][np * 2 + h2];
                        mma_bf16(c, ahi[mt], bh + h2 * 2);
                        mma_bf16(c, ahi[mt], bl + h2 * 2);
                        mma_bf16(c, alo[mt], bh + h2 * 2);
                    }
                }
            }
        }
        __syncthreads();
        s ^= 1;
    }

    const int n2 = (lane & 3) * 2;
#pragma unroll
    for (int mt = 0; mt < 2; ++mt) {
        const int mbase = row0 + wm * 32 + mt * 16 + q;
#pragma unroll
        for (int nt = 0; nt < 8; ++nt) {
            const int gc = col0 + wn * 64 + nt * 8 + n2;
            const float bx = bias[gc], by = bias[gc + 1];
            const float* c = acc[mt][nt];
            if (mbase < M)
                *(float2*)(C + (size_t)mbase * N + gc) =
                    make_float2(c[0] + bx, c[1] + by);
            if (mbase + 8 < M)
                *(float2*)(C + (size_t)(mbase + 8) * N + gc) =
                    make_float2(c[2] + bx, c[3] + by);
        }
    }
}

// ---------------- deformable sampling core --------------------------------
// block = (32,8): warp = head. Phase 1: lane = point, compute 4 (byte-offset,
// weight) pairs, store interleaved. Phase 2: lane = (corner g, channel-quad);
// per point: 1 LDS.64 + 1 LDG.128 + 4 FFMA; cross-corner reduce via 2 shfl.
__global__ __launch_bounds__(256)
void msda_sample_kernel(const float* __restrict__ refp)
{
    __shared__ float4 st[NH][32][2];     // [h][point][(o0,w0,o1,w1),(o2,w2,o3,w3)]

    const int bq   = blockIdx.x;
    const int lane = threadIdx.x;
    const int h    = threadIdx.y;
    const int b    = bq >> 12;

    const float aval = g_qo[(size_t)bq * 768 + h * 32 + lane];
    float mx = aval;
#pragma unroll
    for (int s = 16; s; s >>= 1) mx = fmaxf(mx, __shfl_xor_sync(0xffffffffu, mx, s));
    const float e = __expf(aval - mx);
    float sm = e;
#pragma unroll
    for (int s = 16; s; s >>= 1) sm += __shfl_xor_sync(0xffffffffu, sm, s);
    const float aw = e / sm;

    {
        const int j  = lane;
        const int lv = j >> 3;
        const int Wl = cWL[lv], Hl = cHL[lv];

        const float2 o2 = *(const float2*)(g_qo + (size_t)bq * 768 + 256
                                           + h * 64 + j * 2);
        const float rx = refp[(size_t)bq * 8 + lv * 2];
        const float ry = refp[(size_t)bq * 8 + lv * 2 + 1];

        const float locx = rx + o2.x * cIW[lv];
        const float locy = ry + o2.y * cIH[lv];
        const float gx = 2.f * locx - 1.f;
        const float gy = 2.f * locy - 1.f;
        const float x = (gx + 1.f) * ((float)Wl * 0.5f) - 0.5f;
        const float y = (gy + 1.f) * ((float)Hl * 0.5f) - 0.5f;

        const float xf = floorf(x), yf = floorf(y);
        const float wx = x - xf,    wy = y - yf;
        const int x0 = (int)xf, y0 = (int)yf;
        const int x1 = x0 + 1,  y1 = y0 + 1;

        const bool vx0 = (x0 >= 0) && (x0 < Wl);
        const bool vx1 = (x1 >= 0) && (x1 < Wl);
        const bool vy0 = (y0 >= 0) && (y0 < Hl);
        const bool vy1 = (y1 >= 0) && (y1 < Hl);

        const int xA = min(max(x0, 0), Wl - 1);
        const int xB = min(max(x1, 0), Wl - 1);
        const int yA = min(max(y0, 0), Hl - 1);
        const int yB = min(max(y1, 0), Hl - 1);

        const int base = cST[lv];
        const int off00 = (base + yA * Wl + xA) << 10;
        const int off10 = (base + yA * Wl + xB) << 10;
        const int off01 = (base + yB * Wl + xA) << 10;
        const int off11 = (base + yB * Wl + xB) << 10;

        const float w00 = (vx0 && vy0) ? aw * (1.f - wx) * (1.f - wy) : 0.f;
        const float w10 = (vx1 && vy0) ? aw * wx         * (1.f - wy) : 0.f;
        const float w01 = (vx0 && vy1) ? aw * (1.f - wx) * wy         : 0.f;
        const float w11 = (vx1 && vy1) ? aw * wx         * wy         : 0.f;

        st[h][j][0] = make_float4(__int_as_float(off00), w00,
                                  __int_as_float(off10), w10);
        st[h][j][1] = make_float4(__int_as_float(off01), w01,
                                  __int_as_float(off11), w11);
    }
    __syncwarp();

    // ---- phase 2: lane = (corner, channel quad) ----
    const int g  = lane >> 3;            // corner 0..3
    const int cq = lane & 7;             // channel quad 0..7
    const char* vb = (const char*)(g_v + (size_t)b * LTOT * EMB + h * 32 + cq * 4);
    const float2* ow = (const float2*)&st[h][0][0];   // [point][corner] pairs

    float4 acc = make_float4(0.f, 0.f, 0.f, 0.f);
#pragma unroll 8
    for (int p = 0; p < 32; ++p) {
        const float2 o = ow[p * 4 + g];          // (byte offset, weight)
        const float4 v = *(const float4*)(vb + __float_as_int(o.x));
        acc.x = fmaf(o.y, v.x, acc.x);
        acc.y = fmaf(o.y, v.y, acc.y);
        acc.z = fmaf(o.y, v.z, acc.z);
        acc.w = fmaf(o.y, v.w, acc.w);
    }
    // reduce over 4 corner groups (lanes cq, cq+8, cq+16, cq+24)
#pragma unroll
    for (int s = 8; s <= 16; s <<= 1) {
        acc.x += __shfl_xor_sync(0xffffffffu, acc.x, s);
        acc.y += __shfl_xor_sync(0xffffffffu, acc.y, s);
        acc.z += __shfl_xor_sync(0xffffffffu, acc.z, s);
        acc.w += __shfl_xor_sync(0xffffffffu, acc.w, s);
    }
    if (g == 0)
        *(float4*)(g_tmp + (size_t)bq * EMB + h * 32 + cq * 4) = acc;
}

// ---------------- launch ---------------------------------------------------
extern "C" void kernel_launch(void* const* d_in, const int* in_sizes, int n_in,
                              void* d_out, int out_size)
{
    const float* query  = (const float*)d_in[0];
    const float* value  = (const float*)d_in[1];
    const float* refp   = (const float*)d_in[2];
    const float* W_off  = (const float*)d_in[4];
    const float* b_off  = (const float*)d_in[5];
    const float* W_attn = (const float*)d_in[6];
    const float* b_attn = (const float*)d_in[7];
    const float* W_val  = (const float*)d_in[8];
    const float* b_val  = (const float*)d_in[9];
    const float* W_out  = (const float*)d_in[10];
    const float* b_out  = (const float*)d_in[11];
    float* out = (float*)d_out;

    float *gv, *gqo, *gtmp, *gbqo;
    __nv_bfloat16 *wth, *wtl;
    cudaGetSymbolAddress((void**)&gv,   g_v);
    cudaGetSymbolAddress((void**)&gqo,  g_qo);
    cudaGetSymbolAddress((void**)&gtmp, g_tmp);
    cudaGetSymbolAddress((void**)&gbqo, g_bqo);
    cudaGetSymbolAddress((void**)&wth,  g_wt_hi);
    cudaGetSymbolAddress((void**)&wtl,  g_wt_lo);

    cudaFuncSetAttribute(gemm_tc_kernel,
                         cudaFuncAttributeMaxDynamicSharedMemorySize, SMEM_DYN);

    // 0) weight transpose + bf16 hi/lo split + fused bias
    prep_weights<<<1280, 256>>>(W_val, W_attn, W_off, W_out, b_attn, b_off);

    // 1) value projection -> g_v   [117360 x 256]
    gemm_tc_kernel<<<dim3(2, (MV + 63) / 64), 128, SMEM_DYN>>>(
        value, wth + (size_t)WT_VAL * 256, wtl + (size_t)WT_VAL * 256,
        b_val, gv, MV, 256);

    // 2) fused attn+off -> g_qo    [24576 x 768]
    gemm_tc_kernel<<<dim3(6, MQ / 64), 128, SMEM_DYN>>>(
        query, wth + (size_t)WT_QRY * 256, wtl + (size_t)WT_QRY * 256,
        gbqo, gqo, MQ, 768);

    // 3) softmax + bilinear sampling -> g_tmp
    msda_sample_kernel<<<MQ, dim3(32, 8)>>>(refp);

    // 4) output projection -> d_out
    gemm_tc_kernel<<<dim3(2, MQ / 64), 128, SMEM_DYN>>>(
        gtmp, wth + (size_t)WT_OUT * 256, wtl + (size_t)WT_OUT * 256,
        b_out, out, MQ, 256);
}